// round 15
// baseline (speedup 1.0000x reference)
#include <cuda_runtime.h>
#include <cuda_fp16.h>
#include <stdint.h>
#include <math.h>

#define BATCH 8
#define CCH   256
#define DD    32
#define NN    4096
#define BM    128
#define BN    64
#define NTILES (NN / BN)

// device scratch (allocation-free rule). Q/K split fp16 hi/lo, [b][n][d] packed
__device__ uint32_t g_qh[BATCH * NN * 16];
__device__ uint32_t g_ql[BATCH * NN * 16];
__device__ uint32_t g_kh[BATCH * NN * 16];
__device__ uint32_t g_kl[BATCH * NN * 16];
__device__ uint32_t g_v [BATCH * CCH * NN / 2];   // fp16 [b][c][n]

// pack two floats -> fp16x2 (first arg = low half)
__device__ __forceinline__ uint32_t pkh(float lo, float hi) {
    uint32_t d;
    asm("cvt.rn.f16x2.f32 %0, %1, %2;" : "=r"(d) : "f"(hi), "f"(lo));
    return d;
}
__device__ __forceinline__ float h2f_rn(float v) {
    return __half2float(__float2half_rn(v));
}
__device__ __forceinline__ void ldsm4(uint32_t* r, uint32_t a) {
    asm volatile("ldmatrix.sync.aligned.m8n8.x4.shared.b16 {%0,%1,%2,%3}, [%4];"
        : "=r"(r[0]), "=r"(r[1]), "=r"(r[2]), "=r"(r[3]) : "r"(a));
}
__device__ __forceinline__ void mma16(float* d, const uint32_t* a, uint32_t b0, uint32_t b1) {
    asm volatile("mma.sync.aligned.m16n8k16.row.col.f32.f16.f16.f32 "
        "{%0,%1,%2,%3}, {%4,%5,%6,%7}, {%8,%9}, {%0,%1,%2,%3};"
        : "+f"(d[0]), "+f"(d[1]), "+f"(d[2]), "+f"(d[3])
        : "r"(a[0]), "r"(a[1]), "r"(a[2]), "r"(a[3]), "r"(b0), "r"(b1));
}
__device__ __forceinline__ uint32_t smem_u32(const void* p) {
    uint32_t a;
    asm("{ .reg .u64 t; cvta.to.shared.u64 t, %1; cvt.u32.u64 %0, t; }" : "=r"(a) : "l"(p));
    return a;
}
#define CP16(dst, src) \
    asm volatile("cp.async.cg.shared.global [%0], [%1], 16;" :: "r"(dst), "l"(src) : "memory")
#define CP_COMMIT() asm volatile("cp.async.commit_group;" ::: "memory")
#define CP_WAIT1()  asm volatile("cp.async.wait_group 1;" ::: "memory")

// smem byte offsets (attn)
#define OFF_ALPH 0                          // 128 f32 (per-q rescale alpha)
#define OFF_INV  512                        // 128 f32 (epilogue)
#define OFF_FLG  1024                       // 2 ints (rescale flags, tile parity)
#define OFF_QH   1040                       // 128 x 80B
#define OFF_QL   (OFF_QH + 10240)
#define OFF_KH   (OFF_QL + 10240)           // 2 stages x 64 x 80B
#define OFF_KL   (OFF_KH + 10240)
#define OFF_V    (OFF_KL + 10240)           // 2 stages x 256 x 144B
#define OFF_P    (OFF_V + 73728)            // 128 x 144B
#define SMEM_ATTN (OFF_P + 18432)
#define KSTG 5120
#define VSTG 36864

// ---------------------------------------------------------------------------
// Q/K projection: split fp16 hi/lo [b][n][d]. R = DD = 32.
// ---------------------------------------------------------------------------
__global__ __launch_bounds__(256) void proj_qk(
    const float* __restrict__ W, const float* __restrict__ bias,
    const float* __restrict__ x, uint32_t* __restrict__ outh,
    uint32_t* __restrict__ outl)
{
    __shared__ float Ws[32 * 33];
    __shared__ float Xs[32 * 132];

    const int b  = blockIdx.z;
    const int n0 = blockIdx.x * 128;
    const int tid = threadIdx.x;
    const int ty = tid >> 5, tx = tid & 31;
    const float* xb = x + (size_t)b * CCH * NN;
    uint32_t* oh = outh + (size_t)b * NN * 16;
    uint32_t* ol = outl + (size_t)b * NN * 16;

    float acc[4][4];
    #pragma unroll
    for (int r = 0; r < 4; r++) {
        float bv = bias[ty * 4 + r];
        acc[r][0] = bv; acc[r][1] = bv; acc[r][2] = bv; acc[r][3] = bv;
    }
    for (int c0 = 0; c0 < CCH; c0 += 32) {
        __syncthreads();
        for (int i = tid; i < 32 * 32; i += 256) {
            int r = i >> 5, c = i & 31;
            Ws[r * 33 + c] = W[(size_t)r * CCH + c0 + c];
        }
        for (int i = tid; i < 32 * 32; i += 256) {
            int c = i >> 5, nq = i & 31;
            *(float4*)&Xs[c * 132 + nq * 4] =
                *(const float4*)&xb[(size_t)(c0 + c) * NN + n0 + nq * 4];
        }
        __syncthreads();
        #pragma unroll 8
        for (int kk = 0; kk < 32; kk++) {
            float4 xv = *(const float4*)&Xs[kk * 132 + tx * 4];
            #pragma unroll
            for (int r = 0; r < 4; r++) {
                float wv = Ws[(ty * 4 + r) * 33 + kk];
                acc[r][0] += wv * xv.x; acc[r][1] += wv * xv.y;
                acc[r][2] += wv * xv.z; acc[r][3] += wv * xv.w;
            }
        }
    }
    // write split fp16 [n][d]
    #pragma unroll
    for (int i = 0; i < 4; i++) {
        const int n = n0 + tx * 4 + i;
        float v0 = acc[0][i], v1 = acc[1][i], v2 = acc[2][i], v3 = acc[3][i];
        uint2 H, L;
        H.x = pkh(v0, v1); H.y = pkh(v2, v3);
        L.x = pkh(v0 - h2f_rn(v0), v1 - h2f_rn(v1));
        L.y = pkh(v2 - h2f_rn(v2), v3 - h2f_rn(v3));
        *(uint2*)&oh[(size_t)n * 16 + 2 * ty] = H;
        *(uint2*)&ol[(size_t)n * 16 + 2 * ty] = L;
    }
}

// ---------------------------------------------------------------------------
// V projection writing fp16: g_v[b][c][n]
// ---------------------------------------------------------------------------
__global__ __launch_bounds__(256) void proj_v_f16(
    const float* __restrict__ W, const float* __restrict__ bias,
    const float* __restrict__ x, uint32_t* __restrict__ out)
{
    __shared__ float Ws[32 * 33];
    __shared__ float Xs[32 * 132];
    const int b  = blockIdx.z;
    const int r0 = blockIdx.y * 32;
    const int n0 = blockIdx.x * 128;
    const int tid = threadIdx.x;
    const int ty = tid >> 5, tx = tid & 31;
    const float* xb = x + (size_t)b * CCH * NN;
    uint32_t* ob = out + (size_t)b * CCH * NN / 2;

    float acc[4][4];
    #pragma unroll
    for (int r = 0; r < 4; r++) {
        float bv = bias[r0 + ty * 4 + r];
        acc[r][0] = bv; acc[r][1] = bv; acc[r][2] = bv; acc[r][3] = bv;
    }
    for (int c0 = 0; c0 < CCH; c0 += 32) {
        __syncthreads();
        for (int i = tid; i < 32 * 32; i += 256) {
            int r = i >> 5, c = i & 31;
            Ws[r * 33 + c] = W[(size_t)(r0 + r) * CCH + c0 + c];
        }
        for (int i = tid; i < 32 * 32; i += 256) {
            int c = i >> 5, nq = i & 31;
            *(float4*)&Xs[c * 132 + nq * 4] =
                *(const float4*)&xb[(size_t)(c0 + c) * NN + n0 + nq * 4];
        }
        __syncthreads();
        #pragma unroll 8
        for (int kk = 0; kk < 32; kk++) {
            float4 xv = *(const float4*)&Xs[kk * 132 + tx * 4];
            #pragma unroll
            for (int r = 0; r < 4; r++) {
                float wv = Ws[(ty * 4 + r) * 33 + kk];
                acc[r][0] += wv * xv.x; acc[r][1] += wv * xv.y;
                acc[r][2] += wv * xv.z; acc[r][3] += wv * xv.w;
            }
        }
    }
    #pragma unroll
    for (int r = 0; r < 4; r++) {
        uint2 o2;
        o2.x = pkh(acc[r][0], acc[r][1]);
        o2.y = pkh(acc[r][2], acc[r][3]);
        *(uint2*)&ob[((size_t)(r0 + ty * 4 + r) * NN + n0 + tx * 4) / 2] = o2;
    }
}

// ---------------------------------------------------------------------------
// Flash attention: fp16 m16n8k16 + ldmatrix + cp.async double buffering +
// ONLINE softmax (true running row max; alpha-rescale of accumulator columns
// only on tiles where the max changed — shared-flag uniform branch).
// 256 thr, BM=128 q/CTA. S: warp w owns q [16w,16w+16). PV: warp w owns
// c [32w,32w+32) x all 128 q (o is c-rows x q-cols).
// ---------------------------------------------------------------------------
__global__ __launch_bounds__(256, 1) void attn_kernel(
    const float* __restrict__ x, const float* __restrict__ gammap,
    float* __restrict__ out)
{
    extern __shared__ char sm[];
    const uint32_t sb = smem_u32(sm);
    float* ALPH = (float*)(sm + OFF_ALPH);
    float* INVs = (float*)(sm + OFF_INV);
    int*   flg  = (int*)(sm + OFF_FLG);

    const int b  = blockIdx.y;
    const int q0 = blockIdx.x * BM;
    const int tid = threadIdx.x;
    const int lane = tid & 31;
    const int w = tid >> 5;
    const int g = lane >> 2, tg = lane & 3;
    const int lrow = (lane & 7) + 8 * ((lane >> 3) & 1);
    const int lc16 = (lane >> 4) * 16;

    const char* qhg = (const char*)g_qh + (size_t)b * NN * 64;
    const char* qlg = (const char*)g_ql + (size_t)b * NN * 64;
    const char* khg = (const char*)g_kh + (size_t)b * NN * 64;
    const char* klg = (const char*)g_kl + (size_t)b * NN * 64;
    const char* vg  = (const char*)g_v  + (size_t)b * CCH * NN * 2;

    const int kj_ = tid >> 2, kc_ = tid & 3;

    // ---- prologue: Q tiles + tile 0, one cp.async group ----
    #pragma unroll
    for (int it = 0; it < 4; it++) {
        int idx = tid + it * 256;
        int arr = idx >> 9, rem = idx & 511;
        int q = rem >> 2, c = rem & 3;
        const char* src = (arr ? qlg : qhg) + (size_t)(q0 + q) * 64 + c * 16;
        uint32_t dst = sb + (arr ? OFF_QL : OFF_QH) + q * 80 + c * 16;
        CP16(dst, src);
    }
    {
        CP16(sb + OFF_KH + kj_ * 80 + kc_ * 16, khg + (size_t)kj_ * 64 + kc_ * 16);
        CP16(sb + OFF_KL + kj_ * 80 + kc_ * 16, klg + (size_t)kj_ * 64 + kc_ * 16);
        #pragma unroll
        for (int ch = 0; ch < 8; ch++)
            CP16(sb + OFF_V + tid * 144 + ch * 16, vg + (size_t)tid * NN * 2 + ch * 16);
    }
    CP_COMMIT();

    if (tid < 2) flg[tid] = 0;

    float m_a = -1e30f, m_b = -1e30f;
    float lsa = 0.f, lsb = 0.f;

    float o[2][16][4];
    #pragma unroll
    for (int ct = 0; ct < 2; ct++)
        #pragma unroll
        for (int qt = 0; qt < 16; qt++)
            { o[ct][qt][0]=0.f; o[ct][qt][1]=0.f; o[ct][qt][2]=0.f; o[ct][qt][3]=0.f; }

    uint32_t qh[2][4], ql[2][4];
    bool qloaded = false;

    for (int t = 0; t < NTILES; t++) {
        const int stg = t & 1;
        // issue next tile into the other stage
        if (t + 1 < NTILES) {
            const int m1 = (t + 1) * BN;
            const int ns = (t + 1) & 1;
            CP16(sb + OFF_KH + ns * KSTG + kj_ * 80 + kc_ * 16,
                 khg + (size_t)(m1 + kj_) * 64 + kc_ * 16);
            CP16(sb + OFF_KL + ns * KSTG + kj_ * 80 + kc_ * 16,
                 klg + (size_t)(m1 + kj_) * 64 + kc_ * 16);
            #pragma unroll
            for (int ch = 0; ch < 8; ch++)
                CP16(sb + OFF_V + ns * VSTG + tid * 144 + ch * 16,
                     vg + (size_t)tid * NN * 2 + m1 * 2 + ch * 16);
        }
        CP_COMMIT();
        CP_WAIT1();          // tile t (and Q on t=0) resident
        __syncthreads();

        // clear the OTHER parity's flag (consumed at t-1, set again at t+1;
        // both transitions separated from here by the surrounding barriers)
        if (tid == 0) flg[(t + 1) & 1] = 0;

        if (!qloaded) {      // Q fragments are tile-invariant
            #pragma unroll
            for (int ks = 0; ks < 2; ks++) {
                ldsm4(qh[ks], sb + OFF_QH + (16 * w + lrow) * 80 + ks * 32 + lc16);
                ldsm4(ql[ks], sb + OFF_QL + (16 * w + lrow) * 80 + ks * 32 + lc16);
            }
            qloaded = true;
        }

        // ---- S = Q.K^T (3-term split fp16) ----
        float s[8][4];
        #pragma unroll
        for (int i = 0; i < 32; i++) ((float*)s)[i] = 0.f;
        #pragma unroll
        for (int ks = 0; ks < 2; ks++) {
            uint32_t kb[4][4];
            #pragma unroll
            for (int i = 0; i < 4; i++)
                ldsm4(kb[i], sb + OFF_KH + stg * KSTG + (16 * i + lrow) * 80 + ks * 32 + lc16);
            #pragma unroll
            for (int i = 0; i < 4; i++) {
                mma16(s[2 * i],     qh[ks], kb[i][0], kb[i][2]);
                mma16(s[2 * i + 1], qh[ks], kb[i][1], kb[i][3]);
                mma16(s[2 * i],     ql[ks], kb[i][0], kb[i][2]);
                mma16(s[2 * i + 1], ql[ks], kb[i][1], kb[i][3]);
            }
            #pragma unroll
            for (int i = 0; i < 4; i++)
                ldsm4(kb[i], sb + OFF_KL + stg * KSTG + (16 * i + lrow) * 80 + ks * 32 + lc16);
            #pragma unroll
            for (int i = 0; i < 4; i++) {
                mma16(s[2 * i],     qh[ks], kb[i][0], kb[i][2]);
                mma16(s[2 * i + 1], qh[ks], kb[i][1], kb[i][3]);
            }
        }

        // ---- online softmax: row max, alpha, P = exp(s - m_new) ----
        {
            float ra = -1e30f, rb = -1e30f;
            #pragma unroll
            for (int nt = 0; nt < 8; nt++) {
                ra = fmaxf(ra, fmaxf(s[nt][0], s[nt][1]));
                rb = fmaxf(rb, fmaxf(s[nt][2], s[nt][3]));
            }
            ra = fmaxf(ra, __shfl_xor_sync(0xffffffffu, ra, 1));
            ra = fmaxf(ra, __shfl_xor_sync(0xffffffffu, ra, 2));
            rb = fmaxf(rb, __shfl_xor_sync(0xffffffffu, rb, 1));
            rb = fmaxf(rb, __shfl_xor_sync(0xffffffffu, rb, 2));
            float mna = fmaxf(m_a, ra), mnb = fmaxf(m_b, rb);
            float aa = __expf(m_a - mna), ab = __expf(m_b - mnb);
            m_a = mna; m_b = mnb;
            lsa *= aa; lsb *= ab;
            if (tg == 0) { ALPH[16 * w + g] = aa; ALPH[16 * w + g + 8] = ab; }
            if (aa < 1.f || ab < 1.f) flg[t & 1] = 1;

            char* pr0 = sm + OFF_P + (16 * w + g) * 144 + 4 * tg;
            char* pr1 = sm + OFF_P + (16 * w + g + 8) * 144 + 4 * tg;
            #pragma unroll
            for (int nt = 0; nt < 8; nt++) {
                float p0 = __expf(s[nt][0] - mna);
                float p1 = __expf(s[nt][1] - mna);
                float p2 = __expf(s[nt][2] - mnb);
                float p3 = __expf(s[nt][3] - mnb);
                lsa += p0 + p1; lsb += p2 + p3;
                *(uint32_t*)(pr0 + 16 * nt) = pkh(p0, p1);
                *(uint32_t*)(pr1 + 16 * nt) = pkh(p2, p3);
            }
        }
        __syncthreads();

        // ---- rescale accumulator columns if any row max changed ----
        if (flg[t & 1]) {
            #pragma unroll
            for (int qt = 0; qt < 16; qt++) {
                float a0 = ALPH[8 * qt + 2 * tg];
                float a1 = ALPH[8 * qt + 2 * tg + 1];
                #pragma unroll
                for (int ct = 0; ct < 2; ct++) {
                    o[ct][qt][0] *= a0; o[ct][qt][1] *= a1;
                    o[ct][qt][2] *= a0; o[ct][qt][3] *= a1;
                }
            }
        }

        // ---- O^T[c][q] += V[c][j] . P^T[j][q] ----
        #pragma unroll
        for (int kj = 0; kj < 4; kj++) {
            uint32_t av[2][4], bp[8][4];
            #pragma unroll
            for (int ct = 0; ct < 2; ct++)
                ldsm4(av[ct], sb + OFF_V + stg * VSTG +
                              (32 * w + 16 * ct + lrow) * 144 + kj * 32 + lc16);
            #pragma unroll
            for (int i = 0; i < 8; i++)
                ldsm4(bp[i], sb + OFF_P + (16 * i + lrow) * 144 + kj * 32 + lc16);
            #pragma unroll
            for (int ct = 0; ct < 2; ct++)
                #pragma unroll
                for (int i = 0; i < 8; i++) {
                    mma16(o[ct][2 * i],     av[ct], bp[i][0], bp[i][2]);
                    mma16(o[ct][2 * i + 1], av[ct], bp[i][1], bp[i][3]);
                }
        }
        __syncthreads();   // stage reuse + P/ALPH/flag overwrite protection
    }

    // ---- lsum reduce ----
    lsa += __shfl_xor_sync(0xffffffffu, lsa, 1);
    lsa += __shfl_xor_sync(0xffffffffu, lsa, 2);
    lsb += __shfl_xor_sync(0xffffffffu, lsb, 1);
    lsb += __shfl_xor_sync(0xffffffffu, lsb, 2);
    if (tg == 0) { INVs[16 * w + g] = lsa; INVs[16 * w + g + 8] = lsb; }
    __syncthreads();
    if (tid < 128) INVs[tid] = gammap[0] / INVs[tid];
    __syncthreads();

    // ---- epilogue: out = gamma*O/l + x ----
    const float* xb = x + (size_t)b * CCH * NN;
    float* ob = out + (size_t)b * CCH * NN;
    #pragma unroll
    for (int ct = 0; ct < 2; ct++) {
        const int cr = 32 * w + 16 * ct + g;
        #pragma unroll
        for (int qt = 0; qt < 16; qt++) {
            const int qc = qt * 8 + 2 * tg;
            const float i0 = INVs[qc], i1 = INVs[qc + 1];
            size_t g0 = (size_t)cr * NN + q0 + qc;
            float2 x0 = *(const float2*)&xb[g0];
            *(float2*)&ob[g0] = make_float2(o[ct][qt][0] * i0 + x0.x,
                                            o[ct][qt][1] * i1 + x0.y);
            size_t g1 = (size_t)(cr + 8) * NN + q0 + qc;
            float2 x1 = *(const float2*)&xb[g1];
            *(float2*)&ob[g1] = make_float2(o[ct][qt][2] * i0 + x1.x,
                                            o[ct][qt][3] * i1 + x1.y);
        }
    }
}

// ---------------------------------------------------------------------------
extern "C" void kernel_launch(void* const* d_in, const int* in_sizes, int n_in,
                              void* d_out, int out_size)
{
    const float* x     = (const float*)d_in[0];
    const float* wq    = (const float*)d_in[1];
    const float* bq    = (const float*)d_in[2];
    const float* wk    = (const float*)d_in[3];
    const float* bk    = (const float*)d_in[4];
    const float* wv    = (const float*)d_in[5];
    const float* bv    = (const float*)d_in[6];
    const float* gamma = (const float*)d_in[7];
    float* out = (float*)d_out;

    uint32_t *qh, *ql, *kh, *kl, *vp;
    cudaGetSymbolAddress((void**)&qh, g_qh);
    cudaGetSymbolAddress((void**)&ql, g_ql);
    cudaGetSymbolAddress((void**)&kh, g_kh);
    cudaGetSymbolAddress((void**)&kl, g_kl);
    cudaGetSymbolAddress((void**)&vp, g_v);

    dim3 gqk(NN / 128, 1, BATCH);
    proj_qk<<<gqk, 256>>>(wq, bq, x, qh, ql);
    proj_qk<<<gqk, 256>>>(wk, bk, x, kh, kl);
    dim3 gv(NN / 128, CCH / 32, BATCH);
    proj_v_f16<<<gv, 256>>>(wv, bv, x, vp);

    cudaFuncSetAttribute(attn_kernel,
                         cudaFuncAttributeMaxDynamicSharedMemorySize, SMEM_ATTN);
    dim3 ga(NN / BM, BATCH);
    attn_kernel<<<ga, 256, SMEM_ATTN>>>(x, gamma, out);
}

// round 17
// speedup vs baseline: 1.1149x; 1.1149x over previous
#include <cuda_runtime.h>
#include <cuda_fp16.h>
#include <stdint.h>
#include <math.h>

#define BATCH 8
#define CCH   256
#define DD    32
#define NN    4096
#define BM    128
#define BN    64
#define NTILES (NN / BN)

// device scratch (allocation-free rule). Q/K split fp16 hi/lo, [b][n][d] packed
__device__ uint32_t g_qh[BATCH * NN * 16];
__device__ uint32_t g_ql[BATCH * NN * 16];
__device__ uint32_t g_kh[BATCH * NN * 16];
__device__ uint32_t g_kl[BATCH * NN * 16];
__device__ uint32_t g_v [BATCH * CCH * NN / 2];   // fp16 [b][c][n]

__device__ __forceinline__ uint32_t pkh(float lo, float hi) {
    uint32_t d;
    asm("cvt.rn.f16x2.f32 %0, %1, %2;" : "=r"(d) : "f"(hi), "f"(lo));
    return d;
}
__device__ __forceinline__ float h2f_rn(float v) {
    return __half2float(__float2half_rn(v));
}
__device__ __forceinline__ void ldsm4(uint32_t* r, uint32_t a) {
    asm volatile("ldmatrix.sync.aligned.m8n8.x4.shared.b16 {%0,%1,%2,%3}, [%4];"
        : "=r"(r[0]), "=r"(r[1]), "=r"(r[2]), "=r"(r[3]) : "r"(a));
}
__device__ __forceinline__ void mma16(float* d, const uint32_t* a, uint32_t b0, uint32_t b1) {
    asm volatile("mma.sync.aligned.m16n8k16.row.col.f32.f16.f16.f32 "
        "{%0,%1,%2,%3}, {%4,%5,%6,%7}, {%8,%9}, {%0,%1,%2,%3};"
        : "+f"(d[0]), "+f"(d[1]), "+f"(d[2]), "+f"(d[3])
        : "r"(a[0]), "r"(a[1]), "r"(a[2]), "r"(a[3]), "r"(b0), "r"(b1));
}
__device__ __forceinline__ uint32_t smem_u32(const void* p) {
    uint32_t a;
    asm("{ .reg .u64 t; cvta.to.shared.u64 t, %1; cvt.u32.u64 %0, t; }" : "=r"(a) : "l"(p));
    return a;
}
#define CP16(dst, src) \
    asm volatile("cp.async.cg.shared.global [%0], [%1], 16;" :: "r"(dst), "l"(src) : "memory")
#define CP_COMMIT() asm volatile("cp.async.commit_group;" ::: "memory")
#define CP_WAIT1()  asm volatile("cp.async.wait_group 1;" ::: "memory")

// smem byte offsets (attn)
#define OFF_ALPH 0                          // 128 f32
#define OFF_INV  512                        // 128 f32
#define OFF_RMAX 1024                       // [2][128] f32 row-max halves
#define OFF_LP   2048                       // [2][128] f32 lsum halves
#define OFF_FLG  3072                       // 2 ints
#define OFF_QH   3088                       // 128 x 80B
#define OFF_QL   (OFF_QH + 10240)
#define OFF_KH   (OFF_QL + 10240)           // 2 stages x 64 x 80B
#define OFF_KL   (OFF_KH + 10240)
#define OFF_V    (OFF_KL + 10240)           // 2 stages x 256 x 144B
#define OFF_P    (OFF_V + 73728)            // 128 x 144B
#define SMEM_ATTN (OFF_P + 18432)           // 136208 B
#define KSTG 5120
#define VSTG 36864

// ---------------------------------------------------------------------------
// Q/K projection: split fp16 hi/lo [b][n][d]. R = DD = 32.
// ---------------------------------------------------------------------------
__global__ __launch_bounds__(256) void proj_qk(
    const float* __restrict__ W, const float* __restrict__ bias,
    const float* __restrict__ x, uint32_t* __restrict__ outh,
    uint32_t* __restrict__ outl)
{
    __shared__ float Ws[32 * 33];
    __shared__ float Xs[32 * 132];

    const int b  = blockIdx.z;
    const int n0 = blockIdx.x * 128;
    const int tid = threadIdx.x;
    const int ty = tid >> 5, tx = tid & 31;
    const float* xb = x + (size_t)b * CCH * NN;
    uint32_t* oh = outh + (size_t)b * NN * 16;
    uint32_t* ol = outl + (size_t)b * NN * 16;

    float acc[4][4];
    #pragma unroll
    for (int r = 0; r < 4; r++) {
        float bv = bias[ty * 4 + r];
        acc[r][0] = bv; acc[r][1] = bv; acc[r][2] = bv; acc[r][3] = bv;
    }
    for (int c0 = 0; c0 < CCH; c0 += 32) {
        __syncthreads();
        for (int i = tid; i < 32 * 32; i += 256) {
            int r = i >> 5, c = i & 31;
            Ws[r * 33 + c] = W[(size_t)r * CCH + c0 + c];
        }
        for (int i = tid; i < 32 * 32; i += 256) {
            int c = i >> 5, nq = i & 31;
            *(float4*)&Xs[c * 132 + nq * 4] =
                *(const float4*)&xb[(size_t)(c0 + c) * NN + n0 + nq * 4];
        }
        __syncthreads();
        #pragma unroll 8
        for (int kk = 0; kk < 32; kk++) {
            float4 xv = *(const float4*)&Xs[kk * 132 + tx * 4];
            #pragma unroll
            for (int r = 0; r < 4; r++) {
                float wv = Ws[(ty * 4 + r) * 33 + kk];
                acc[r][0] += wv * xv.x; acc[r][1] += wv * xv.y;
                acc[r][2] += wv * xv.z; acc[r][3] += wv * xv.w;
            }
        }
    }
    #pragma unroll
    for (int i = 0; i < 4; i++) {
        const int n = n0 + tx * 4 + i;
        float v0 = acc[0][i], v1 = acc[1][i], v2 = acc[2][i], v3 = acc[3][i];
        uint2 H, L;
        H.x = pkh(v0, v1); H.y = pkh(v2, v3);
        L.x = pkh(v0 - h2f_rn(v0), v1 - h2f_rn(v1));
        L.y = pkh(v2 - h2f_rn(v2), v3 - h2f_rn(v3));
        *(uint2*)&oh[(size_t)n * 16 + 2 * ty] = H;
        *(uint2*)&ol[(size_t)n * 16 + 2 * ty] = L;
    }
}

// ---------------------------------------------------------------------------
// V projection writing fp16: g_v[b][c][n]
// ---------------------------------------------------------------------------
__global__ __launch_bounds__(256) void proj_v_f16(
    const float* __restrict__ W, const float* __restrict__ bias,
    const float* __restrict__ x, uint32_t* __restrict__ out)
{
    __shared__ float Ws[32 * 33];
    __shared__ float Xs[32 * 132];
    const int b  = blockIdx.z;
    const int r0 = blockIdx.y * 32;
    const int n0 = blockIdx.x * 128;
    const int tid = threadIdx.x;
    const int ty = tid >> 5, tx = tid & 31;
    const float* xb = x + (size_t)b * CCH * NN;
    uint32_t* ob = out + (size_t)b * CCH * NN / 2;

    float acc[4][4];
    #pragma unroll
    for (int r = 0; r < 4; r++) {
        float bv = bias[r0 + ty * 4 + r];
        acc[r][0] = bv; acc[r][1] = bv; acc[r][2] = bv; acc[r][3] = bv;
    }
    for (int c0 = 0; c0 < CCH; c0 += 32) {
        __syncthreads();
        for (int i = tid; i < 32 * 32; i += 256) {
            int r = i >> 5, c = i & 31;
            Ws[r * 33 + c] = W[(size_t)(r0 + r) * CCH + c0 + c];
        }
        for (int i = tid; i < 32 * 32; i += 256) {
            int c = i >> 5, nq = i & 31;
            *(float4*)&Xs[c * 132 + nq * 4] =
                *(const float4*)&xb[(size_t)(c0 + c) * NN + n0 + nq * 4];
        }
        __syncthreads();
        #pragma unroll 8
        for (int kk = 0; kk < 32; kk++) {
            float4 xv = *(const float4*)&Xs[kk * 132 + tx * 4];
            #pragma unroll
            for (int r = 0; r < 4; r++) {
                float wv = Ws[(ty * 4 + r) * 33 + kk];
                acc[r][0] += wv * xv.x; acc[r][1] += wv * xv.y;
                acc[r][2] += wv * xv.z; acc[r][3] += wv * xv.w;
            }
        }
    }
    #pragma unroll
    for (int r = 0; r < 4; r++) {
        uint2 o2;
        o2.x = pkh(acc[r][0], acc[r][1]);
        o2.y = pkh(acc[r][2], acc[r][3]);
        *(uint2*)&ob[((size_t)(r0 + ty * 4 + r) * NN + n0 + tx * 4) / 2] = o2;
    }
}

// ---------------------------------------------------------------------------
// Flash attention: fp16 m16n8k16 + ldmatrix + cp.async double buffering +
// online softmax. 512 threads = 16 warps, BM=128 q/CTA.
// S-phase: warp pair (mi = w>>1 owns 16 q) x (jh = w&1 owns 32 of 64 keys);
//          row max merged across the pair via RMAX smem.
// PV-phase: warp owns 16 channels x all 128 q  -> o[16][4] = 64 regs.
// ---------------------------------------------------------------------------
__global__ __launch_bounds__(512, 1) void attn_kernel(
    const float* __restrict__ x, const float* __restrict__ gammap,
    float* __restrict__ out)
{
    extern __shared__ char sm[];
    const uint32_t sb = smem_u32(sm);
    float* ALPH = (float*)(sm + OFF_ALPH);
    float* INVs = (float*)(sm + OFF_INV);
    float* RMAX = (float*)(sm + OFF_RMAX);
    float* LP   = (float*)(sm + OFF_LP);
    int*   flg  = (int*)(sm + OFF_FLG);

    const int b  = blockIdx.y;
    const int q0 = blockIdx.x * BM;
    const int tid = threadIdx.x;
    const int lane = tid & 31;
    const int w = tid >> 5;
    const int g = lane >> 2, tg = lane & 3;
    const int lrow = (lane & 7) + 8 * ((lane >> 3) & 1);
    const int lc16 = (lane >> 4) * 16;
    const int mi = w >> 1, jh = w & 1;

    const char* qhg = (const char*)g_qh + (size_t)b * NN * 64;
    const char* qlg = (const char*)g_ql + (size_t)b * NN * 64;
    const char* khg = (const char*)g_kh + (size_t)b * NN * 64;
    const char* klg = (const char*)g_kl + (size_t)b * NN * 64;
    const char* vg  = (const char*)g_v  + (size_t)b * CCH * NN * 2;

    // K fill: 512 threads = 2 arrays x 64 rows x 4 chunks, one CP16 each
    const int karr = tid >> 8, krem = tid & 255;
    const int kj_ = krem >> 2, kc_ = krem & 3;
    // V fill: c = tid>>1, chunks (tid&1)*4 .. +3
    const int vc_ = tid >> 1, vh_ = (tid & 1) * 4;

    // ---- prologue: Q tiles + tile 0 ----
    #pragma unroll
    for (int it = 0; it < 2; it++) {
        int idx = tid + it * 512;
        int arr = idx >> 9, rem = idx & 511;
        int q = rem >> 2, c = rem & 3;
        const char* src = (arr ? qlg : qhg) + (size_t)(q0 + q) * 64 + c * 16;
        uint32_t dst = sb + (arr ? OFF_QL : OFF_QH) + q * 80 + c * 16;
        CP16(dst, src);
    }
    {
        const char* ksrc = (karr ? klg : khg) + (size_t)kj_ * 64 + kc_ * 16;
        CP16(sb + (karr ? OFF_KL : OFF_KH) + kj_ * 80 + kc_ * 16, ksrc);
        #pragma unroll
        for (int ch = 0; ch < 4; ch++)
            CP16(sb + OFF_V + vc_ * 144 + (vh_ + ch) * 16,
                 vg + (size_t)vc_ * NN * 2 + (vh_ + ch) * 16);
    }
    CP_COMMIT();

    if (tid < 2) flg[tid] = 0;

    float m_a = -1e30f, m_b = -1e30f;
    float lsa = 0.f, lsb = 0.f;

    float o[16][4];
    #pragma unroll
    for (int qt = 0; qt < 16; qt++)
        { o[qt][0]=0.f; o[qt][1]=0.f; o[qt][2]=0.f; o[qt][3]=0.f; }

    uint32_t qh[2][4], ql[2][4];
    bool qloaded = false;

    for (int t = 0; t < NTILES; t++) {
        const int stg = t & 1;
        if (t + 1 < NTILES) {
            const int m1 = (t + 1) * BN;
            const int ns = (t + 1) & 1;
            const char* ksrc = (karr ? klg : khg) + (size_t)(m1 + kj_) * 64 + kc_ * 16;
            CP16(sb + (karr ? OFF_KL : OFF_KH) + ns * KSTG + kj_ * 80 + kc_ * 16, ksrc);
            #pragma unroll
            for (int ch = 0; ch < 4; ch++)
                CP16(sb + OFF_V + ns * VSTG + vc_ * 144 + (vh_ + ch) * 16,
                     vg + (size_t)vc_ * NN * 2 + m1 * 2 + (vh_ + ch) * 16);
        }
        CP_COMMIT();
        CP_WAIT1();
        __syncthreads();

        if (tid == 0) flg[(t + 1) & 1] = 0;

        if (!qloaded) {
            #pragma unroll
            for (int ks = 0; ks < 2; ks++) {
                ldsm4(qh[ks], sb + OFF_QH + (16 * mi + lrow) * 80 + ks * 32 + lc16);
                ldsm4(ql[ks], sb + OFF_QL + (16 * mi + lrow) * 80 + ks * 32 + lc16);
            }
            qloaded = true;
        }

        // ---- S = Q.K^T for this warp's 32-key half (3-term split fp16) ----
        float s[4][4];
        #pragma unroll
        for (int i = 0; i < 16; i++) ((float*)s)[i] = 0.f;
        #pragma unroll
        for (int ks = 0; ks < 2; ks++) {
            uint32_t kb[2][4];
            #pragma unroll
            for (int i = 0; i < 2; i++)
                ldsm4(kb[i], sb + OFF_KH + stg * KSTG +
                             (16 * (2 * jh + i) + lrow) * 80 + ks * 32 + lc16);
            #pragma unroll
            for (int i = 0; i < 2; i++) {
                mma16(s[2 * i],     qh[ks], kb[i][0], kb[i][2]);
                mma16(s[2 * i + 1], qh[ks], kb[i][1], kb[i][3]);
                mma16(s[2 * i],     ql[ks], kb[i][0], kb[i][2]);
                mma16(s[2 * i + 1], ql[ks], kb[i][1], kb[i][3]);
            }
            #pragma unroll
            for (int i = 0; i < 2; i++)
                ldsm4(kb[i], sb + OFF_KL + stg * KSTG +
                             (16 * (2 * jh + i) + lrow) * 80 + ks * 32 + lc16);
            #pragma unroll
            for (int i = 0; i < 2; i++) {
                mma16(s[2 * i],     qh[ks], kb[i][0], kb[i][2]);
                mma16(s[2 * i + 1], qh[ks], kb[i][1], kb[i][3]);
            }
        }

        // ---- half row-max -> RMAX ----
        {
            float ra = -1e30f, rb = -1e30f;
            #pragma unroll
            for (int nt = 0; nt < 4; nt++) {
                ra = fmaxf(ra, fmaxf(s[nt][0], s[nt][1]));
                rb = fmaxf(rb, fmaxf(s[nt][2], s[nt][3]));
            }
            ra = fmaxf(ra, __shfl_xor_sync(0xffffffffu, ra, 1));
            ra = fmaxf(ra, __shfl_xor_sync(0xffffffffu, ra, 2));
            rb = fmaxf(rb, __shfl_xor_sync(0xffffffffu, rb, 1));
            rb = fmaxf(rb, __shfl_xor_sync(0xffffffffu, rb, 2));
            if (tg == 0) {
                RMAX[jh * 128 + 16 * mi + g]     = ra;
                RMAX[jh * 128 + 16 * mi + g + 8] = rb;
            }
        }
        __syncthreads();

        // ---- merge halves, alpha, P = exp(s - m_new) ----
        {
            float ra = fmaxf(RMAX[16 * mi + g],     RMAX[128 + 16 * mi + g]);
            float rb = fmaxf(RMAX[16 * mi + g + 8], RMAX[128 + 16 * mi + g + 8]);
            float mna = fmaxf(m_a, ra), mnb = fmaxf(m_b, rb);
            float aa = __expf(m_a - mna), ab = __expf(m_b - mnb);
            m_a = mna; m_b = mnb;
            lsa *= aa; lsb *= ab;
            if (jh == 0 && tg == 0) {
                ALPH[16 * mi + g] = aa; ALPH[16 * mi + g + 8] = ab;
            }
            if (aa < 1.f || ab < 1.f) flg[t & 1] = 1;

            char* pr0 = sm + OFF_P + (16 * mi + g) * 144 + jh * 64 + 4 * tg;
            char* pr1 = sm + OFF_P + (16 * mi + g + 8) * 144 + jh * 64 + 4 * tg;
            #pragma unroll
            for (int nt = 0; nt < 4; nt++) {
                float p0 = __expf(s[nt][0] - mna);
                float p1 = __expf(s[nt][1] - mna);
                float p2 = __expf(s[nt][2] - mnb);
                float p3 = __expf(s[nt][3] - mnb);
                lsa += p0 + p1; lsb += p2 + p3;
                *(uint32_t*)(pr0 + 16 * nt) = pkh(p0, p1);
                *(uint32_t*)(pr1 + 16 * nt) = pkh(p2, p3);
            }
        }
        __syncthreads();

        // ---- rescale accumulator columns if any row max changed ----
        if (flg[t & 1]) {
            #pragma unroll
            for (int qt = 0; qt < 16; qt++) {
                float a0 = ALPH[8 * qt + 2 * tg];
                float a1 = ALPH[8 * qt + 2 * tg + 1];
                o[qt][0] *= a0; o[qt][1] *= a1;
                o[qt][2] *= a0; o[qt][3] *= a1;
            }
        }

        // ---- O^T[c][q] += V[c][j] . P^T[j][q], warp owns 16 c ----
        #pragma unroll
        for (int kj = 0; kj < 4; kj++) {
            uint32_t av[4];
            ldsm4(av, sb + OFF_V + stg * VSTG + (16 * w + lrow) * 144 + kj * 32 + lc16);
            #pragma unroll
            for (int i = 0; i < 8; i++) {
                uint32_t bp[4];
                ldsm4(bp, sb + OFF_P + (16 * i + lrow) * 144 + kj * 32 + lc16);
                mma16(o[2 * i],     av, bp[0], bp[2]);
                mma16(o[2 * i + 1], av, bp[1], bp[3]);
            }
        }
        __syncthreads();
    }

    // ---- lsum: reduce within warp, merge halves via LP ----
    lsa += __shfl_xor_sync(0xffffffffu, lsa, 1);
    lsa += __shfl_xor_sync(0xffffffffu, lsa, 2);
    lsb += __shfl_xor_sync(0xffffffffu, lsb, 1);
    lsb += __shfl_xor_sync(0xffffffffu, lsb, 2);
    if (tg == 0) {
        LP[jh * 128 + 16 * mi + g]     = lsa;
        LP[jh * 128 + 16 * mi + g + 8] = lsb;
    }
    __syncthreads();
    if (tid < 128) INVs[tid] = gammap[0] / (LP[tid] + LP[128 + tid]);
    __syncthreads();

    // ---- epilogue: out = gamma*O/l + x ----
    const float* xb = x + (size_t)b * CCH * NN;
    float* ob = out + (size_t)b * CCH * NN;
    const int cr = 16 * w + g;
    #pragma unroll
    for (int qt = 0; qt < 16; qt++) {
        const int qc = qt * 8 + 2 * tg;
        const float i0 = INVs[qc], i1 = INVs[qc + 1];
        size_t g0 = (size_t)cr * NN + q0 + qc;
        float2 x0 = *(const float2*)&xb[g0];
        *(float2*)&ob[g0] = make_float2(o[qt][0] * i0 + x0.x,
                                        o[qt][1] * i1 + x0.y);
        size_t g1 = (size_t)(cr + 8) * NN + q0 + qc;
        float2 x1 = *(const float2*)&xb[g1];
        *(float2*)&ob[g1] = make_float2(o[qt][2] * i0 + x1.x,
                                        o[qt][3] * i1 + x1.y);
    }
}

// ---------------------------------------------------------------------------
extern "C" void kernel_launch(void* const* d_in, const int* in_sizes, int n_in,
                              void* d_out, int out_size)
{
    const float* x     = (const float*)d_in[0];
    const float* wq    = (const float*)d_in[1];
    const float* bq    = (const float*)d_in[2];
    const float* wk    = (const float*)d_in[3];
    const float* bk    = (const float*)d_in[4];
    const float* wv    = (const float*)d_in[5];
    const float* bv    = (const float*)d_in[6];
    const float* gamma = (const float*)d_in[7];
    float* out = (float*)d_out;

    uint32_t *qh, *ql, *kh, *kl, *vp;
    cudaGetSymbolAddress((void**)&qh, g_qh);
    cudaGetSymbolAddress((void**)&ql, g_ql);
    cudaGetSymbolAddress((void**)&kh, g_kh);
    cudaGetSymbolAddress((void**)&kl, g_kl);
    cudaGetSymbolAddress((void**)&vp, g_v);

    dim3 gqk(NN / 128, 1, BATCH);
    proj_qk<<<gqk, 256>>>(wq, bq, x, qh, ql);
    proj_qk<<<gqk, 256>>>(wk, bk, x, kh, kl);
    dim3 gv(NN / 128, CCH / 32, BATCH);
    proj_v_f16<<<gv, 256>>>(wv, bv, x, vp);

    cudaFuncSetAttribute(attn_kernel,
                         cudaFuncAttributeMaxDynamicSharedMemorySize, SMEM_ATTN);
    dim3 ga(NN / BM, BATCH);
    attn_kernel<<<ga, 512, SMEM_ATTN>>>(x, gamma, out);
}